// round 1
// baseline (speedup 1.0000x reference)
#include <cuda_runtime.h>
#include <cstdint>

#define N_NODES 100000
#define N_EDGES 1600000
#define IN_CH   128
#define TYPE_EMB 32
#define FEAT    160          // IN_CH + TYPE_EMB
#define OUT_CH  128
#define N_REL   8
#define N_BASES 8
#define NSLOT   (N_REL + 1)  // slot 0 = h, slots 1..8 = per-relation sums
#define KTOT    (FEAT * NSLOT)  // 1440

// ---------------- device scratch (static: no allocation allowed) ----------------
// A matrix: [node][slot][FEAT]  (slot0 = h, slots 1..8 = relation sums) = 576 MB
__device__ float g_A[(size_t)N_NODES * KTOT];
// per-(node, relation) edge counts (float; counts are small, exact in fp32)
__device__ float g_cnt[N_NODES * N_REL];
// stacked weights: rows 0..159 = root_w, rows 160+r*160.. = weight[r] = sum_b comp[r,b]*bases[b]
__device__ float g_W[KTOT * OUT_CH];

// ---------------- kernel 1: zero scratch ----------------
__global__ void k_zero() {
    const size_t n4 = (size_t)N_NODES * KTOT / 4;
    float4 z = make_float4(0.f, 0.f, 0.f, 0.f);
    size_t stride = (size_t)gridDim.x * blockDim.x;
    for (size_t i = (size_t)blockIdx.x * blockDim.x + threadIdx.x; i < n4; i += stride)
        reinterpret_cast<float4*>(g_A)[i] = z;
    for (size_t i = (size_t)blockIdx.x * blockDim.x + threadIdx.x;
         i < (size_t)N_NODES * N_REL; i += stride)
        g_cnt[i] = 0.f;
}

// ---------------- kernel 2: build stacked weight matrix ----------------
__global__ void k_build_w(const float* __restrict__ bases,
                          const float* __restrict__ comp,
                          const float* __restrict__ root_w) {
    int idx = blockIdx.x * blockDim.x + threadIdx.x;  // over KTOT*OUT_CH
    if (idx >= KTOT * OUT_CH) return;
    int k = idx / OUT_CH;
    int o = idx - k * OUT_CH;
    float v;
    if (k < FEAT) {
        v = root_w[k * OUT_CH + o];
    } else {
        int r = k / FEAT - 1;
        int f = k % FEAT;
        v = 0.f;
#pragma unroll
        for (int b = 0; b < N_BASES; ++b)
            v = fmaf(comp[r * N_BASES + b], bases[((size_t)b * FEAT + f) * OUT_CH + o], v);
    }
    g_W[idx] = v;
}

// ---------------- kernel 3: h = concat(x, emb[type]) into slot 0 ----------------
__global__ void k_build_h(const float* __restrict__ x,
                          const int* __restrict__ ntype,
                          const float* __restrict__ emb) {
    int i = blockIdx.x * blockDim.x + threadIdx.x;  // over N_NODES*FEAT
    if (i >= N_NODES * FEAT) return;
    int n = i / FEAT;
    int f = i - n * FEAT;
    float v = (f < IN_CH) ? x[(size_t)n * IN_CH + f]
                          : emb[ntype[n] * TYPE_EMB + (f - IN_CH)];
    g_A[(size_t)n * KTOT + f] = v;
}

// ---------------- kernel 4: edge scatter (warp per edge, vectorized RED) ----------------
__device__ __forceinline__ void red_add_v4(float* addr, float4 v) {
    asm volatile("red.global.add.v4.f32 [%0], {%1, %2, %3, %4};"
                 :: "l"(addr), "f"(v.x), "f"(v.y), "f"(v.z), "f"(v.w)
                 : "memory");
}

__global__ void k_scatter(const int* __restrict__ edge_index,
                          const int* __restrict__ edge_type) {
    int e    = (blockIdx.x * blockDim.x + threadIdx.x) >> 5;
    int lane = threadIdx.x & 31;
    if (e >= N_EDGES) return;
    int src = edge_index[e];
    int dst = edge_index[N_EDGES + e];
    int r   = edge_type[e];

    const float4* hs = reinterpret_cast<const float4*>(g_A + (size_t)src * KTOT); // slot 0: 40 float4
    float* dbase = g_A + (size_t)dst * KTOT + FEAT + (size_t)r * FEAT;            // slot r+1

    float4 v = hs[lane];
    red_add_v4(dbase + lane * 4, v);
    if (lane < 8) {
        float4 v2 = hs[32 + lane];
        red_add_v4(dbase + (32 + lane) * 4, v2);
    }
    if (lane == 0) atomicAdd(&g_cnt[(size_t)dst * N_REL + r], 1.0f);
}

// ---------------- kernel 5: fused GEMM  out = A_scaled @ W + bias, ReLU ----------------
// A_scaled[n][k] = g_A[n][k] * scale(n, slot(k)),  scale(n,0)=1, scale(n,s)=1/max(cnt,1)
#define BM 128
#define BN 128
#define BK 32

__global__ __launch_bounds__(256, 2)
void k_gemm(const float* __restrict__ bias, float* __restrict__ out) {
    __shared__ float As[BK][BM + 4];      // [k][m]
    __shared__ float Bs[BK][BN];          // [k][n]
    __shared__ float sScale[BM][NSLOT + 1];  // [m][slot], padded

    const int tid = threadIdx.x;
    const int n0  = blockIdx.x * BM;
    const int ty  = tid >> 4;   // 0..15 -> node micro-rows
    const int tx  = tid & 15;   // 0..15 -> out micro-cols

    // per-node per-slot scales
    for (int i = tid; i < BM * NSLOT; i += 256) {
        int m = i / NSLOT, s = i - m * NSLOT;
        float sc = 1.0f;
        int node = n0 + m;
        if (s > 0) {
            float c = (node < N_NODES) ? g_cnt[(size_t)node * N_REL + (s - 1)] : 1.0f;
            sc = 1.0f / fmaxf(c, 1.0f);
        }
        sScale[m][s] = sc;
    }

    float bb[8];
#pragma unroll
    for (int j = 0; j < 8; ++j) bb[j] = bias[tx * 8 + j];

    float acc[8][8];
#pragma unroll
    for (int i = 0; i < 8; ++i)
#pragma unroll
        for (int j = 0; j < 8; ++j) acc[i][j] = 0.f;

    __syncthreads();

    const int NTILES = KTOT / BK;  // 45, exact
    for (int kt = 0; kt < NTILES; ++kt) {
        const int k0   = kt * BK;
        const int slot = k0 / FEAT;  // constant per tile (FEAT % BK == 0)

        // stage A tile (with scaling), transposed to [k][m]
#pragma unroll
        for (int p = 0; p < 4; ++p) {
            int q  = p * 256 + tid;      // 0..1023 float4 slots
            int m  = q >> 3;             // 0..127
            int kq = (q & 7) * 4;        // 0,4,...,28
            float4 v = make_float4(0.f, 0.f, 0.f, 0.f);
            int node = n0 + m;
            if (node < N_NODES)
                v = *reinterpret_cast<const float4*>(g_A + (size_t)node * KTOT + k0 + kq);
            float sc = sScale[m][slot];
            As[kq + 0][m] = v.x * sc;
            As[kq + 1][m] = v.y * sc;
            As[kq + 2][m] = v.z * sc;
            As[kq + 3][m] = v.w * sc;
        }
        // stage B tile
#pragma unroll
        for (int p = 0; p < 4; ++p) {
            int q  = p * 256 + tid;      // 0..1023
            int kI = q >> 5;             // 0..31
            int n4 = (q & 31) * 4;       // 0..124
            float4 w = *reinterpret_cast<const float4*>(g_W + (size_t)(k0 + kI) * OUT_CH + n4);
            *reinterpret_cast<float4*>(&Bs[kI][n4]) = w;
        }
        __syncthreads();

#pragma unroll 8
        for (int kk = 0; kk < BK; ++kk) {
            float4 a0 = *reinterpret_cast<const float4*>(&As[kk][ty * 8]);
            float4 a1 = *reinterpret_cast<const float4*>(&As[kk][ty * 8 + 4]);
            float4 b0 = *reinterpret_cast<const float4*>(&Bs[kk][tx * 8]);
            float4 b1 = *reinterpret_cast<const float4*>(&Bs[kk][tx * 8 + 4]);
            float a[8] = {a0.x, a0.y, a0.z, a0.w, a1.x, a1.y, a1.z, a1.w};
            float b[8] = {b0.x, b0.y, b0.z, b0.w, b1.x, b1.y, b1.z, b1.w};
#pragma unroll
            for (int i = 0; i < 8; ++i)
#pragma unroll
                for (int j = 0; j < 8; ++j)
                    acc[i][j] = fmaf(a[i], b[j], acc[i][j]);
        }
        __syncthreads();
    }

    // epilogue: bias + ReLU
#pragma unroll
    for (int i = 0; i < 8; ++i) {
        int node = n0 + ty * 8 + i;
        if (node >= N_NODES) continue;
        float4 o0, o1;
        o0.x = fmaxf(acc[i][0] + bb[0], 0.f);
        o0.y = fmaxf(acc[i][1] + bb[1], 0.f);
        o0.z = fmaxf(acc[i][2] + bb[2], 0.f);
        o0.w = fmaxf(acc[i][3] + bb[3], 0.f);
        o1.x = fmaxf(acc[i][4] + bb[4], 0.f);
        o1.y = fmaxf(acc[i][5] + bb[5], 0.f);
        o1.z = fmaxf(acc[i][6] + bb[6], 0.f);
        o1.w = fmaxf(acc[i][7] + bb[7], 0.f);
        float* op = out + (size_t)node * OUT_CH + tx * 8;
        *reinterpret_cast<float4*>(op)     = o0;
        *reinterpret_cast<float4*>(op + 4) = o1;
    }
}

// ---------------- launch ----------------
extern "C" void kernel_launch(void* const* d_in, const int* in_sizes, int n_in,
                              void* d_out, int out_size) {
    const float* x        = (const float*)d_in[0];
    const int*   ntype    = (const int*)  d_in[1];
    const int*   eidx     = (const int*)  d_in[2];
    const int*   etype    = (const int*)  d_in[3];
    const float* emb      = (const float*)d_in[4];
    const float* bases    = (const float*)d_in[5];
    const float* comp     = (const float*)d_in[6];
    const float* root_w   = (const float*)d_in[7];
    const float* bias     = (const float*)d_in[8];
    float*       out      = (float*)d_out;

    // 1) zero accumulators
    k_zero<<<2048, 256>>>();
    // 2) stacked weights [1440 x 128]
    k_build_w<<<(KTOT * OUT_CH + 255) / 256, 256>>>(bases, comp, root_w);
    // 3) h = [x | emb[type]] into slot 0
    k_build_h<<<(N_NODES * FEAT + 255) / 256, 256>>>(x, ntype, emb);
    // 4) edge scatter (warp per edge)
    k_scatter<<<(N_EDGES * 32 + 255) / 256, 256>>>(eidx, etype);
    // 5) fused scaled-GEMM + bias + ReLU
    k_gemm<<<(N_NODES + BM - 1) / BM, 256>>>(bias, out);
}

// round 3
// speedup vs baseline: 1.6231x; 1.6231x over previous
#include <cuda_runtime.h>
#include <cuda_bf16.h>
#include <cstdint>

#define N_NODES 100000
#define N_EDGES 1600000
#define IN_CH   128
#define TYPE_EMB 32
#define FEAT    160
#define OUT_CH  128
#define N_REL   8
#define N_BASES 8
#define NSLOT   (N_REL + 1)
#define KTOT    (FEAT * NSLOT)   // 1440
#define KPAD    1472             // 23 * 64
#define KCH     64
#define NCHUNK  23

// Arch-feature gate: tcgen05 only exists on the 'a' targets. The harness also
// builds a plain compute_103 pass; that pass gets a stub body.
#if defined(__CUDA_ARCH_FEAT_SM103_ALL) || defined(__CUDA_ARCH_FEAT_SM100_ALL) || \
    defined(__CUDA_ARCH_FEAT_SM101_ALL) || \
    (defined(__CUDA_ARCH_SPECIFIC__) && (__CUDA_ARCH_SPECIFIC__ >= 1000))
#define HAS_TCGEN05 1
#else
#define HAS_TCGEN05 0
#endif

// ---------------- device scratch ----------------
__device__ float g_A[(size_t)N_NODES * KTOT];          // [node][slot][FEAT], slot0 = h
__device__ float g_cnt[N_NODES * N_REL];
__device__ float g_W[KTOT * OUT_CH];                   // fp32 [k][o] (fallback path)
__device__ __nv_bfloat16 g_Bh[OUT_CH * KPAD];          // W^T hi, [o][k]
__device__ __nv_bfloat16 g_Bl[OUT_CH * KPAD];          // W^T lo
__device__ int g_mma_ok;                               // 1 if tcgen05 kernel did the work

// ================= PTX helpers =================
__device__ __forceinline__ uint32_t smem_u32(const void* p) {
    uint32_t a;
    asm("{ .reg .u64 t; cvta.to.shared.u64 t, %1; cvt.u32.u64 %0, t; }" : "=r"(a) : "l"(p));
    return a;
}
#define MBARRIER_INIT(addr, cnt) \
    asm volatile("mbarrier.init.shared.b64 [%0], %1;" :: "r"((uint32_t)(addr)), "r"((uint32_t)(cnt)) : "memory")
#define MBARRIER_INVAL(addr) \
    asm volatile("mbarrier.inval.shared.b64 [%0];" :: "r"((uint32_t)(addr)) : "memory")
#define MBARRIER_WAIT_PARITY(mbar_smem_addr, phase_parity) do { \
    uint32_t _mbar = (uint32_t)(mbar_smem_addr); \
    uint32_t _parity = (uint32_t)(phase_parity); \
    uint32_t _done; \
    asm volatile( \
        "{\n\t.reg .pred p;\n\t" \
        "mbarrier.try_wait.parity.acquire.cta.shared::cta.b64 p, [%1], %2;\n\t" \
        "selp.b32 %0, 1, 0, p;\n\t}" \
        : "=r"(_done) : "r"(_mbar), "r"(_parity) : "memory"); \
    if (!_done) { \
        asm volatile( \
            "{\n\t.reg .pred P1;\n\t" \
            "WAIT_LOOP_%=:\n\t" \
            "mbarrier.try_wait.parity.acquire.cta.shared::cta.b64 P1, [%0], %1, 0x989680;\n\t" \
            "@P1 bra.uni WAIT_DONE_%=;\n\t" \
            "bra.uni WAIT_LOOP_%=;\n\t" \
            "WAIT_DONE_%=:\n\t}" \
            :: "r"(_mbar), "r"(_parity) : "memory"); \
    } \
} while(0)

#if HAS_TCGEN05
__device__ __forceinline__ uint32_t elect_one() {
    uint32_t pred;
    asm volatile("{\n\t.reg .pred p;\n\telect.sync _|p, 0xFFFFFFFF;\n\tselp.b32 %0, 1, 0, p;\n\t}" : "=r"(pred));
    return pred;
}
#define TCGEN05_ALLOC(smem_addr, nCols) \
    asm volatile("tcgen05.alloc.cta_group::1.sync.aligned.shared::cta.b32 [%0], %1;" \
        :: "r"((uint32_t)(smem_addr)), "r"((uint32_t)(nCols)) : "memory")
#define TCGEN05_DEALLOC(tmem_addr, nCols) \
    asm volatile("tcgen05.dealloc.cta_group::1.sync.aligned.b32 %0, %1;" :: "r"(tmem_addr), "r"((uint32_t)(nCols)))
#define TCGEN05_RELINQ() \
    asm volatile("tcgen05.relinquish_alloc_permit.cta_group::1.sync.aligned;")
#define TCGEN05_COMMIT(mbar) \
    asm volatile("tcgen05.commit.cta_group::1.mbarrier::arrive::one.shared::cluster.b64 [%0];" \
        :: "r"((uint32_t)(mbar)) : "memory")
#define TCGEN05_FENCE_AFTER()  asm volatile("tcgen05.fence::after_thread_sync;" ::: "memory")
#define TCGEN05_FENCE_BEFORE() asm volatile("tcgen05.fence::before_thread_sync;" ::: "memory")
#define TCGEN05_WAIT_LD() asm volatile("tcgen05.wait::ld.sync.aligned;" ::: "memory")
#define TCGEN05_LD_32X32B_X32(r, tmem_addr) \
    asm volatile( \
        "tcgen05.ld.sync.aligned.32x32b.x32.b32 " \
        "{%0, %1, %2, %3, %4, %5, %6, %7, " \
        " %8, %9, %10, %11, %12, %13, %14, %15, " \
        " %16, %17, %18, %19, %20, %21, %22, %23, " \
        " %24, %25, %26, %27, %28, %29, %30, %31}, [%32];" \
        : "=r"((r)[0]),  "=r"((r)[1]),  "=r"((r)[2]),  "=r"((r)[3]), \
          "=r"((r)[4]),  "=r"((r)[5]),  "=r"((r)[6]),  "=r"((r)[7]), \
          "=r"((r)[8]),  "=r"((r)[9]),  "=r"((r)[10]), "=r"((r)[11]), \
          "=r"((r)[12]), "=r"((r)[13]), "=r"((r)[14]), "=r"((r)[15]), \
          "=r"((r)[16]), "=r"((r)[17]), "=r"((r)[18]), "=r"((r)[19]), \
          "=r"((r)[20]), "=r"((r)[21]), "=r"((r)[22]), "=r"((r)[23]), \
          "=r"((r)[24]), "=r"((r)[25]), "=r"((r)[26]), "=r"((r)[27]), \
          "=r"((r)[28]), "=r"((r)[29]), "=r"((r)[30]), "=r"((r)[31]) \
        : "r"(tmem_addr))

static constexpr uint64_t SMEM_DESC_BASE_SW128 =
    (uint64_t(2)  << 61) | (uint64_t(1) << 46) | (uint64_t(64) << 32) | (uint64_t(1) << 16);
#define MAKE_SMEM_DESC(base_addr) (SMEM_DESC_BASE_SW128 | ((uint64_t)((base_addr) >> 4) & 0x3FFF))

// idesc: dtype=F32, atype=BF16, btype=BF16, N=128, M=128 (kind::f16)
#define MMA_IDESC 0x8200490u

__device__ __forceinline__ void mma_f16_ss(uint32_t d, uint64_t a_desc, uint64_t b_desc, bool acc) {
    uint32_t en = acc ? 1u : 0u;
    asm volatile(
        "{\n\t.reg .pred p;\n\t"
        "setp.ne.u32 p, %5, 0;\n\t"
        "tcgen05.mma.cta_group::1.kind::f16 [%0], %1, %2, %3, {%4, %4, %4, %4}, p;\n\t"
        "}"
        :: "r"(d), "l"(a_desc), "l"(b_desc), "r"(MMA_IDESC), "r"(0u), "r"(en)
        : "memory");
}
#endif  // HAS_TCGEN05

// ---------------- kernel 1: zero relation slots + counts ----------------
__global__ void k_zero() {
    const size_t n4 = (size_t)N_NODES * (N_REL * FEAT) / 4;
    float4 z = make_float4(0.f, 0.f, 0.f, 0.f);
    size_t stride = (size_t)gridDim.x * blockDim.x;
    for (size_t i = (size_t)blockIdx.x * blockDim.x + threadIdx.x; i < n4; i += stride) {
        size_t n = i / 320;
        size_t j = i - n * 320;
        *reinterpret_cast<float4*>(g_A + n * KTOT + FEAT + j * 4) = z;
    }
    for (size_t i = (size_t)blockIdx.x * blockDim.x + threadIdx.x;
         i < (size_t)N_NODES * N_REL; i += stride)
        g_cnt[i] = 0.f;
}

// ---------------- kernel 2: stacked weights (fp32 + bf16 hi/lo transposed) ----------------
__global__ void k_build_wt(const float* __restrict__ bases,
                           const float* __restrict__ comp,
                           const float* __restrict__ root_w) {
    int idx = blockIdx.x * blockDim.x + threadIdx.x;   // over OUT_CH*KPAD
    if (idx >= OUT_CH * KPAD) return;
    int o = idx / KPAD;
    int k = idx - o * KPAD;
    float v = 0.f;
    if (k < FEAT) {
        v = root_w[k * OUT_CH + o];
    } else if (k < KTOT) {
        int r = k / FEAT - 1;
        int f = k - (r + 1) * FEAT;
#pragma unroll
        for (int b = 0; b < N_BASES; ++b)
            v = fmaf(comp[r * N_BASES + b], bases[((size_t)b * FEAT + f) * OUT_CH + o], v);
    }
    __nv_bfloat16 hi = __float2bfloat16(v);
    g_Bh[idx] = hi;
    g_Bl[idx] = __float2bfloat16(v - __bfloat162float(hi));
    if (k < KTOT) g_W[k * OUT_CH + o] = v;   // fp32 copy for fallback GEMM
}

// ---------------- kernel 3: h = concat(x, emb[type]) ----------------
__global__ void k_build_h(const float* __restrict__ x,
                          const int* __restrict__ ntype,
                          const float* __restrict__ emb) {
    int i = blockIdx.x * blockDim.x + threadIdx.x;
    if (i >= N_NODES * FEAT) return;
    int n = i / FEAT;
    int f = i - n * FEAT;
    float v = (f < IN_CH) ? x[(size_t)n * IN_CH + f]
                          : emb[ntype[n] * TYPE_EMB + (f - IN_CH)];
    g_A[(size_t)n * KTOT + f] = v;
}

// ---------------- kernel 4: edge scatter ----------------
__device__ __forceinline__ void red_add_v4(float* addr, float4 v) {
    asm volatile("red.global.add.v4.f32 [%0], {%1, %2, %3, %4};"
                 :: "l"(addr), "f"(v.x), "f"(v.y), "f"(v.z), "f"(v.w)
                 : "memory");
}

__global__ void k_scatter(const int* __restrict__ edge_index,
                          const int* __restrict__ edge_type) {
    int e    = (blockIdx.x * blockDim.x + threadIdx.x) >> 5;
    int lane = threadIdx.x & 31;
    if (e >= N_EDGES) return;
    int src = edge_index[e];
    int dst = edge_index[N_EDGES + e];
    int r   = edge_type[e];

    const float4* hs = reinterpret_cast<const float4*>(g_A + (size_t)src * KTOT);
    float* dbase = g_A + (size_t)dst * KTOT + FEAT + (size_t)r * FEAT;

    float4 v = hs[lane];
    red_add_v4(dbase + lane * 4, v);
    if (lane < 8) {
        float4 v2 = hs[32 + lane];
        red_add_v4(dbase + (32 + lane) * 4, v2);
    }
    if (lane == 0) atomicAdd(&g_cnt[(size_t)dst * N_REL + r], 1.0f);
}

// ---------------- kernel 5: tcgen05 bf16-split GEMM + bias + ReLU ----------------
#define SM_TILE0   8192
#define TILE_BYTES 16384
#define GEMM_SMEM  (SM_TILE0 + 8 * TILE_BYTES)   // 139264

__global__ __launch_bounds__(256, 1)
void k_gemm_mma(const float* __restrict__ bias, float* __restrict__ out) {
#if HAS_TCGEN05
    extern __shared__ char smem[];
    const uint32_t smem_base = smem_u32(smem);
    const int tid  = threadIdx.x;
    const int wid  = tid >> 5;
    const int lane = tid & 31;
    const int n0   = blockIdx.x * 128;

    if (tid == 0 && blockIdx.x == 0) g_mma_ok = 1;

    float* sBias  = reinterpret_cast<float*>(smem + 64);
    float* sScale = reinterpret_cast<float*>(smem + 576);

    if (wid == 0) {
        TCGEN05_ALLOC(smem_base + 0, 128);
        TCGEN05_RELINQ();
    }
    if (tid == 0) {
        MBARRIER_INIT(smem_base + 8, 1);
        MBARRIER_INIT(smem_base + 16, 1);
    }
    if (tid < 128) sBias[tid] = bias[tid];
    for (int i = tid; i < 128 * 9; i += 256) {
        int m = i / 9, s = i - m * 9;
        float sc = 1.0f;
        int node = n0 + m;
        if (s > 0 && node < N_NODES)
            sc = 1.0f / fmaxf(g_cnt[(size_t)node * N_REL + (s - 1)], 1.0f);
        sScale[i] = sc;
    }
    __syncthreads();

    uint32_t tmem;
    asm volatile("ld.shared.b32 %0, [%1];" : "=r"(tmem) : "r"(smem_base));

    int ph0 = 0, ph1 = 0;
    for (int i = 0; i < NCHUNK; ++i) {
        const int b = i & 1;
        if (i >= 2) {
            if (b == 0) { MBARRIER_WAIT_PARITY(smem_base + 8,  ph0); ph0 ^= 1; }
            else        { MBARRIER_WAIT_PARITY(smem_base + 16, ph1); ph1 ^= 1; }
        }
        char* tp = smem + SM_TILE0 + b * 4 * TILE_BYTES;
        const uint32_t tb = smem_base + SM_TILE0 + (uint32_t)b * 4 * TILE_BYTES;
        const int kbase = i * KCH;

        // ---- stage A (fp32 -> scaled bf16 hi/lo, SW128) ----
#pragma unroll
        for (int p = 0; p < 8; ++p) {
            int q   = p * 256 + tid;       // 0..2047
            int row = q >> 4;              // 0..127
            int c4  = (q & 15) << 2;       // 0..60
            int k   = kbase + c4;
            float4 v = make_float4(0.f, 0.f, 0.f, 0.f);
            int node = n0 + row;
            if (node < N_NODES && k < KTOT)
                v = *reinterpret_cast<const float4*>(g_A + (size_t)node * KTOT + k);
            int slot = k / FEAT; if (slot > 8) slot = 8;
            float sc = sScale[row * 9 + slot];
            float f0 = v.x * sc, f1 = v.y * sc, f2 = v.z * sc, f3 = v.w * sc;
            __nv_bfloat162 h01 = __floats2bfloat162_rn(f0, f1);
            __nv_bfloat162 h23 = __floats2bfloat162_rn(f2, f3);
            float r0 = f0 - __bfloat162float(h01.x);
            float r1 = f1 - __bfloat162float(h01.y);
            float r2 = f2 - __bfloat162float(h23.x);
            float r3 = f3 - __bfloat162float(h23.y);
            __nv_bfloat162 l01 = __floats2bfloat162_rn(r0, r1);
            __nv_bfloat162 l23 = __floats2bfloat162_rn(r2, r3);
            uint32_t off = (uint32_t)(row * 128 + c4 * 2);
            uint32_t sw  = off ^ ((off >> 3) & 0x70);
            uint2 hi2 = make_uint2(*reinterpret_cast<uint32_t*>(&h01),
                                   *reinterpret_cast<uint32_t*>(&h23));
            uint2 lo2 = make_uint2(*reinterpret_cast<uint32_t*>(&l01),
                                   *reinterpret_cast<uint32_t*>(&l23));
            *reinterpret_cast<uint2*>(tp + sw)              = hi2;  // Ah
            *reinterpret_cast<uint2*>(tp + TILE_BYTES + sw) = lo2;  // Al
        }
        // ---- stage B (bf16 hi/lo, SW128) ----
#pragma unroll
        for (int p = 0; p < 4; ++p) {
            int q   = p * 256 + tid;       // 0..1023
            int row = q >> 3;              // 0..127
            int w   = q & 7;               // 0..7
            const uint4* sh = reinterpret_cast<const uint4*>(g_Bh + (size_t)row * KPAD + kbase);
            const uint4* sl = reinterpret_cast<const uint4*>(g_Bl + (size_t)row * KPAD + kbase);
            uint32_t off = (uint32_t)(row * 128 + w * 16);
            uint32_t sw  = off ^ ((off >> 3) & 0x70);
            *reinterpret_cast<uint4*>(tp + 2 * TILE_BYTES + sw) = sh[w];
            *reinterpret_cast<uint4*>(tp + 3 * TILE_BYTES + sw) = sl[w];
        }
        __syncthreads();

        if (wid == 0) {
            asm volatile("fence.proxy.async.shared::cta;" ::: "memory");
            if (elect_one()) {
                uint64_t dAh = MAKE_SMEM_DESC(tb);
                uint64_t dAl = MAKE_SMEM_DESC(tb + TILE_BYTES);
                uint64_t dBh = MAKE_SMEM_DESC(tb + 2 * TILE_BYTES);
                uint64_t dBl = MAKE_SMEM_DESC(tb + 3 * TILE_BYTES);
#pragma unroll
                for (int s = 0; s < 4; ++s) {
                    mma_f16_ss(tmem, dAh + s * 2, dBh + s * 2, (i > 0) || (s > 0));
                    mma_f16_ss(tmem, dAh + s * 2, dBl + s * 2, true);
                    mma_f16_ss(tmem, dAl + s * 2, dBh + s * 2, true);
                }
                TCGEN05_COMMIT(smem_base + 8 + (uint32_t)b * 8);
            }
        }
    }

    MBARRIER_WAIT_PARITY(smem_base + 8,  ph0);
    MBARRIER_WAIT_PARITY(smem_base + 16, ph1);
    TCGEN05_FENCE_AFTER();

    // ---- epilogue ----
    {
        int rsub = wid & 3;
        int c0   = (wid >> 2) * 64;
        int node = n0 + rsub * 32 + lane;
#pragma unroll
        for (int g = 0; g < 2; ++g) {
            uint32_t regs[32];
            TCGEN05_LD_32X32B_X32(regs, tmem + (uint32_t)(c0 + g * 32));
            TCGEN05_WAIT_LD();
            if (node < N_NODES) {
                float* op = out + (size_t)node * OUT_CH + c0 + g * 32;
#pragma unroll
                for (int j4 = 0; j4 < 8; ++j4) {
                    float4 o;
                    o.x = fmaxf(__uint_as_float(regs[j4 * 4 + 0]) + sBias[c0 + g * 32 + j4 * 4 + 0], 0.f);
                    o.y = fmaxf(__uint_as_float(regs[j4 * 4 + 1]) + sBias[c0 + g * 32 + j4 * 4 + 1], 0.f);
                    o.z = fmaxf(__uint_as_float(regs[j4 * 4 + 2]) + sBias[c0 + g * 32 + j4 * 4 + 2], 0.f);
                    o.w = fmaxf(__uint_as_float(regs[j4 * 4 + 3]) + sBias[c0 + g * 32 + j4 * 4 + 3], 0.f);
                    *reinterpret_cast<float4*>(op + j4 * 4) = o;
                }
            }
        }
    }
    TCGEN05_FENCE_BEFORE();
    __syncthreads();
    if (tid == 0) {
        MBARRIER_INVAL(smem_base + 8);
        MBARRIER_INVAL(smem_base + 16);
    }
    __syncthreads();
    if (wid == 0) TCGEN05_DEALLOC(tmem, 128);
#else
    // Stub for non-'a' target: signal fallback.
    if (threadIdx.x == 0 && blockIdx.x == 0) g_mma_ok = 0;
#endif
}

// ---------------- kernel 6: fp32 fallback GEMM (runs only if MMA stubbed) ----------------
#define BM 128
#define BK 32

__global__ __launch_bounds__(256, 2)
void k_gemm_fp32(const float* __restrict__ bias, float* __restrict__ out) {
    if (g_mma_ok) return;

    __shared__ float As[BK][BM + 4];
    __shared__ float Bs[BK][OUT_CH];
    __shared__ float sScale[BM][NSLOT + 1];

    const int tid = threadIdx.x;
    const int n0  = blockIdx.x * BM;
    const int ty  = tid >> 4;
    const int tx  = tid & 15;

    for (int i = tid; i < BM * NSLOT; i += 256) {
        int m = i / NSLOT, s = i - m * NSLOT;
        float sc = 1.0f;
        int node = n0 + m;
        if (s > 0 && node < N_NODES)
            sc = 1.0f / fmaxf(g_cnt[(size_t)node * N_REL + (s - 1)], 1.0f);
        sScale[m][s] = sc;
    }
    float bb[8];
#pragma unroll
    for (int j = 0; j < 8; ++j) bb[j] = bias[tx * 8 + j];
    float acc[8][8];
#pragma unroll
    for (int i = 0; i < 8; ++i)
#pragma unroll
        for (int j = 0; j < 8; ++j) acc[i][j] = 0.f;
    __syncthreads();

    for (int kt = 0; kt < KTOT / BK; ++kt) {
        const int k0   = kt * BK;
        const int slot = k0 / FEAT;
#pragma unroll
        for (int p = 0; p < 4; ++p) {
            int q = p * 256 + tid;
            int m = q >> 3;
            int kq = (q & 7) * 4;
            float4 v = make_float4(0.f, 0.f, 0.f, 0.f);
            int node = n0 + m;
            if (node < N_NODES)
                v = *reinterpret_cast<const float4*>(g_A + (size_t)node * KTOT + k0 + kq);
            float sc = sScale[m][slot];
            As[kq + 0][m] = v.x * sc; As[kq + 1][m] = v.y * sc;
            As[kq + 2][m] = v.z * sc; As[kq + 3][m] = v.w * sc;
        }
#pragma unroll
        for (int p = 0; p < 4; ++p) {
            int q = p * 256 + tid;
            int kI = q >> 5;
            int n4 = (q & 31) * 4;
            *reinterpret_cast<float4*>(&Bs[kI][n4]) =
                *reinterpret_cast<const float4*>(g_W + (size_t)(k0 + kI) * OUT_CH + n4);
        }
        __syncthreads();
#pragma unroll 8
        for (int kk = 0; kk < BK; ++kk) {
            float4 a0 = *reinterpret_cast<const float4*>(&As[kk][ty * 8]);
            float4 a1 = *reinterpret_cast<const float4*>(&As[kk][ty * 8 + 4]);
            float4 b0 = *reinterpret_cast<const float4*>(&Bs[kk][tx * 8]);
            float4 b1 = *reinterpret_cast<const float4*>(&Bs[kk][tx * 8 + 4]);
            float a[8] = {a0.x, a0.y, a0.z, a0.w, a1.x, a1.y, a1.z, a1.w};
            float b[8] = {b0.x, b0.y, b0.z, b0.w, b1.x, b1.y, b1.z, b1.w};
#pragma unroll
            for (int i = 0; i < 8; ++i)
#pragma unroll
                for (int j = 0; j < 8; ++j)
                    acc[i][j] = fmaf(a[i], b[j], acc[i][j]);
        }
        __syncthreads();
    }
#pragma unroll
    for (int i = 0; i < 8; ++i) {
        int node = n0 + ty * 8 + i;
        if (node >= N_NODES) continue;
        float* op = out + (size_t)node * OUT_CH + tx * 8;
#pragma unroll
        for (int j = 0; j < 8; ++j)
            op[j] = fmaxf(acc[i][j] + bb[j], 0.f);
    }
}

// ---------------- launch ----------------
extern "C" void kernel_launch(void* const* d_in, const int* in_sizes, int n_in,
                              void* d_out, int out_size) {
    const float* x      = (const float*)d_in[0];
    const int*   ntype  = (const int*)  d_in[1];
    const int*   eidx   = (const int*)  d_in[2];
    const int*   etype  = (const int*)  d_in[3];
    const float* emb    = (const float*)d_in[4];
    const float* bases  = (const float*)d_in[5];
    const float* comp   = (const float*)d_in[6];
    const float* root_w = (const float*)d_in[7];
    const float* bias   = (const float*)d_in[8];
    float*       out    = (float*)d_out;

    static bool attr_done = false;
    if (!attr_done) {
        cudaFuncSetAttribute(k_gemm_mma, cudaFuncAttributeMaxDynamicSharedMemorySize, GEMM_SMEM);
        attr_done = true;
    }

    k_zero<<<2048, 256>>>();
    k_build_wt<<<(OUT_CH * KPAD + 255) / 256, 256>>>(bases, comp, root_w);
    k_build_h<<<(N_NODES * FEAT + 255) / 256, 256>>>(x, ntype, emb);
    k_scatter<<<(N_EDGES * 32 + 255) / 256, 256>>>(eidx, etype);
    k_gemm_mma<<<(N_NODES + 127) / 128, 256, GEMM_SMEM>>>(bias, out);
    k_gemm_fp32<<<(N_NODES + BM - 1) / BM, 256>>>(bias, out);
}

// round 4
// speedup vs baseline: 2.2941x; 1.4133x over previous
#include <cuda_runtime.h>
#include <cuda_bf16.h>
#include <cstdint>

#define N_NODES 100000
#define N_EDGES 1600000
#define IN_CH   128
#define TYPE_EMB 32
#define FEAT    160
#define OUT_CH  128
#define N_REL   8
#define N_BASES 8
#define NSLOT   (N_REL + 1)
#define KTOT    (FEAT * NSLOT)   // 1440
#define KPAD    1472             // 23 * 64
#define KCH     64
#define NCHUNK  23
#define NKEY    (N_NODES * N_REL)        // 800000
#define NSCANBLK ((NKEY + 1023) / 1024)  // 782

// Arch-feature gate: tcgen05 only exists on the 'a' targets.
#if defined(__CUDA_ARCH_FEAT_SM103_ALL) || defined(__CUDA_ARCH_FEAT_SM100_ALL) || \
    defined(__CUDA_ARCH_FEAT_SM101_ALL) || \
    (defined(__CUDA_ARCH_SPECIFIC__) && (__CUDA_ARCH_SPECIFIC__ >= 1000))
#define HAS_TCGEN05 1
#else
#define HAS_TCGEN05 0
#endif

// ---------------- device scratch ----------------
__device__ float g_A[(size_t)N_NODES * KTOT];          // [node][slot][FEAT], slot0 = h
__device__ float g_cnt[NKEY];                          // [dst*8+r]
__device__ float g_W[KTOT * OUT_CH];                   // fp32 (fallback path)
__device__ __nv_bfloat16 g_Bh[OUT_CH * KPAD];          // W^T hi, [o][k]
__device__ __nv_bfloat16 g_Bl[OUT_CH * KPAD];          // W^T lo
__device__ int g_mma_ok;

// CSR scratch
__device__ int g_hist[NKEY];
__device__ int g_rowptr[NKEY + 1];
__device__ int g_cursor[NKEY];
__device__ int g_aux[NSCANBLK];
__device__ int g_auxs[NSCANBLK];
__device__ int g_esrc[N_EDGES];

// ================= PTX helpers =================
__device__ __forceinline__ uint32_t smem_u32(const void* p) {
    uint32_t a;
    asm("{ .reg .u64 t; cvta.to.shared.u64 t, %1; cvt.u32.u64 %0, t; }" : "=r"(a) : "l"(p));
    return a;
}
#define MBARRIER_INIT(addr, cnt) \
    asm volatile("mbarrier.init.shared.b64 [%0], %1;" :: "r"((uint32_t)(addr)), "r"((uint32_t)(cnt)) : "memory")
#define MBARRIER_INVAL(addr) \
    asm volatile("mbarrier.inval.shared.b64 [%0];" :: "r"((uint32_t)(addr)) : "memory")
#define MBARRIER_WAIT_PARITY(mbar_smem_addr, phase_parity) do { \
    uint32_t _mbar = (uint32_t)(mbar_smem_addr); \
    uint32_t _parity = (uint32_t)(phase_parity); \
    uint32_t _done; \
    asm volatile( \
        "{\n\t.reg .pred p;\n\t" \
        "mbarrier.try_wait.parity.acquire.cta.shared::cta.b64 p, [%1], %2;\n\t" \
        "selp.b32 %0, 1, 0, p;\n\t}" \
        : "=r"(_done) : "r"(_mbar), "r"(_parity) : "memory"); \
    if (!_done) { \
        asm volatile( \
            "{\n\t.reg .pred P1;\n\t" \
            "WAIT_LOOP_%=:\n\t" \
            "mbarrier.try_wait.parity.acquire.cta.shared::cta.b64 P1, [%0], %1, 0x989680;\n\t" \
            "@P1 bra.uni WAIT_DONE_%=;\n\t" \
            "bra.uni WAIT_LOOP_%=;\n\t" \
            "WAIT_DONE_%=:\n\t}" \
            :: "r"(_mbar), "r"(_parity) : "memory"); \
    } \
} while(0)

#if HAS_TCGEN05
__device__ __forceinline__ uint32_t elect_one() {
    uint32_t pred;
    asm volatile("{\n\t.reg .pred p;\n\telect.sync _|p, 0xFFFFFFFF;\n\tselp.b32 %0, 1, 0, p;\n\t}" : "=r"(pred));
    return pred;
}
#define TCGEN05_ALLOC(smem_addr, nCols) \
    asm volatile("tcgen05.alloc.cta_group::1.sync.aligned.shared::cta.b32 [%0], %1;" \
        :: "r"((uint32_t)(smem_addr)), "r"((uint32_t)(nCols)) : "memory")
#define TCGEN05_DEALLOC(tmem_addr, nCols) \
    asm volatile("tcgen05.dealloc.cta_group::1.sync.aligned.b32 %0, %1;" :: "r"(tmem_addr), "r"((uint32_t)(nCols)))
#define TCGEN05_RELINQ() \
    asm volatile("tcgen05.relinquish_alloc_permit.cta_group::1.sync.aligned;")
#define TCGEN05_COMMIT(mbar) \
    asm volatile("tcgen05.commit.cta_group::1.mbarrier::arrive::one.shared::cluster.b64 [%0];" \
        :: "r"((uint32_t)(mbar)) : "memory")
#define TCGEN05_FENCE_AFTER()  asm volatile("tcgen05.fence::after_thread_sync;" ::: "memory")
#define TCGEN05_FENCE_BEFORE() asm volatile("tcgen05.fence::before_thread_sync;" ::: "memory")
#define TCGEN05_WAIT_LD() asm volatile("tcgen05.wait::ld.sync.aligned;" ::: "memory")
#define TCGEN05_LD_32X32B_X32(r, tmem_addr) \
    asm volatile( \
        "tcgen05.ld.sync.aligned.32x32b.x32.b32 " \
        "{%0, %1, %2, %3, %4, %5, %6, %7, " \
        " %8, %9, %10, %11, %12, %13, %14, %15, " \
        " %16, %17, %18, %19, %20, %21, %22, %23, " \
        " %24, %25, %26, %27, %28, %29, %30, %31}, [%32];" \
        : "=r"((r)[0]),  "=r"((r)[1]),  "=r"((r)[2]),  "=r"((r)[3]), \
          "=r"((r)[4]),  "=r"((r)[5]),  "=r"((r)[6]),  "=r"((r)[7]), \
          "=r"((r)[8]),  "=r"((r)[9]),  "=r"((r)[10]), "=r"((r)[11]), \
          "=r"((r)[12]), "=r"((r)[13]), "=r"((r)[14]), "=r"((r)[15]), \
          "=r"((r)[16]), "=r"((r)[17]), "=r"((r)[18]), "=r"((r)[19]), \
          "=r"((r)[20]), "=r"((r)[21]), "=r"((r)[22]), "=r"((r)[23]), \
          "=r"((r)[24]), "=r"((r)[25]), "=r"((r)[26]), "=r"((r)[27]), \
          "=r"((r)[28]), "=r"((r)[29]), "=r"((r)[30]), "=r"((r)[31]) \
        : "r"(tmem_addr))

static constexpr uint64_t SMEM_DESC_BASE_SW128 =
    (uint64_t(2)  << 61) | (uint64_t(1) << 46) | (uint64_t(64) << 32) | (uint64_t(1) << 16);
#define MAKE_SMEM_DESC(base_addr) (SMEM_DESC_BASE_SW128 | ((uint64_t)((base_addr) >> 4) & 0x3FFF))

#define MMA_IDESC 0x8200490u

__device__ __forceinline__ void mma_f16_ss(uint32_t d, uint64_t a_desc, uint64_t b_desc, bool acc) {
    uint32_t en = acc ? 1u : 0u;
    asm volatile(
        "{\n\t.reg .pred p;\n\t"
        "setp.ne.u32 p, %5, 0;\n\t"
        "tcgen05.mma.cta_group::1.kind::f16 [%0], %1, %2, %3, {%4, %4, %4, %4}, p;\n\t"
        "}"
        :: "r"(d), "l"(a_desc), "l"(b_desc), "r"(MMA_IDESC), "r"(0u), "r"(en)
        : "memory");
}
#endif  // HAS_TCGEN05

// ---------------- CSR pipeline ----------------
__global__ void k_zero_meta() {
    int i = blockIdx.x * blockDim.x + threadIdx.x;
    if (i < NKEY) g_hist[i] = 0;
}

__global__ void k_hist(const int* __restrict__ edge_index,
                       const int* __restrict__ edge_type) {
    int e = blockIdx.x * blockDim.x + threadIdx.x;
    if (e >= N_EDGES) return;
    int dst = edge_index[N_EDGES + e];
    int r   = edge_type[e];
    atomicAdd(&g_hist[dst * N_REL + r], 1);
}

// per-block (1024) exclusive scan; block sums to g_aux
__global__ void k_scan1() {
    __shared__ int s[1024];
    int tid = threadIdx.x;
    int i = blockIdx.x * 1024 + tid;
    int v = (i < NKEY) ? g_hist[i] : 0;
    s[tid] = v;
    __syncthreads();
#pragma unroll
    for (int o = 1; o < 1024; o <<= 1) {
        int t = (tid >= o) ? s[tid - o] : 0;
        __syncthreads();
        s[tid] += t;
        __syncthreads();
    }
    if (i <= NKEY && i < NKEY) g_rowptr[i] = s[tid] - v;  // exclusive, pre-offset
    if (tid == 1023) g_aux[blockIdx.x] = s[1023];
}

__global__ void k_scan2() {
    __shared__ int s[1024];
    int tid = threadIdx.x;
    int v = (tid < NSCANBLK) ? g_aux[tid] : 0;
    s[tid] = v;
    __syncthreads();
#pragma unroll
    for (int o = 1; o < 1024; o <<= 1) {
        int t = (tid >= o) ? s[tid - o] : 0;
        __syncthreads();
        s[tid] += t;
        __syncthreads();
    }
    if (tid < NSCANBLK) g_auxs[tid] = s[tid] - v;  // exclusive
}

__global__ void k_scan3() {
    int i = blockIdx.x * blockDim.x + threadIdx.x;
    if (i < NKEY) {
        int v = g_rowptr[i] + g_auxs[i >> 10];
        g_rowptr[i] = v;
        g_cursor[i] = v;
    }
    if (i == 0) g_rowptr[NKEY] = N_EDGES;
}

__global__ void k_scatter_pos(const int* __restrict__ edge_index,
                              const int* __restrict__ edge_type) {
    int e = blockIdx.x * blockDim.x + threadIdx.x;
    if (e >= N_EDGES) return;
    int src = edge_index[e];
    int dst = edge_index[N_EDGES + e];
    int r   = edge_type[e];
    int pos = atomicAdd(&g_cursor[dst * N_REL + r], 1);
    g_esrc[pos] = src;
}

// ---------------- aggregation: warp per (dst, rel), register accumulate ----------------
__global__ __launch_bounds__(256)
void k_aggregate() {
    int w    = (blockIdx.x * blockDim.x + threadIdx.x) >> 5;   // 0..NKEY-1
    int lane = threadIdx.x & 31;
    if (w >= NKEY) return;
    int beg = g_rowptr[w];
    int end = g_rowptr[w + 1];
    float a0 = 0.f, a1 = 0.f, a2 = 0.f, a3 = 0.f, a4 = 0.f;
    for (int e = beg; e < end; ++e) {
        int src = g_esrc[e];
        const float* hp = g_A + (size_t)src * KTOT;
        a0 += hp[lane];
        a1 += hp[lane + 32];
        a2 += hp[lane + 64];
        a3 += hp[lane + 96];
        a4 += hp[lane + 128];
    }
    int dst = w >> 3;
    int r   = w & 7;
    float* op = g_A + (size_t)dst * KTOT + FEAT + (size_t)r * FEAT;
    op[lane]       = a0;
    op[lane + 32]  = a1;
    op[lane + 64]  = a2;
    op[lane + 96]  = a3;
    op[lane + 128] = a4;
    if (lane == 0) g_cnt[w] = (float)(end - beg);
}

// ---------------- weights (fp32 + bf16 hi/lo transposed) ----------------
__global__ void k_build_wt(const float* __restrict__ bases,
                           const float* __restrict__ comp,
                           const float* __restrict__ root_w) {
    int idx = blockIdx.x * blockDim.x + threadIdx.x;
    if (idx >= OUT_CH * KPAD) return;
    int o = idx / KPAD;
    int k = idx - o * KPAD;
    float v = 0.f;
    if (k < FEAT) {
        v = root_w[k * OUT_CH + o];
    } else if (k < KTOT) {
        int r = k / FEAT - 1;
        int f = k - (r + 1) * FEAT;
#pragma unroll
        for (int b = 0; b < N_BASES; ++b)
            v = fmaf(comp[r * N_BASES + b], bases[((size_t)b * FEAT + f) * OUT_CH + o], v);
    }
    __nv_bfloat16 hi = __float2bfloat16(v);
    g_Bh[idx] = hi;
    g_Bl[idx] = __float2bfloat16(v - __bfloat162float(hi));
    if (k < KTOT) g_W[k * OUT_CH + o] = v;
}

// ---------------- h = concat(x, emb[type]) ----------------
__global__ void k_build_h(const float* __restrict__ x,
                          const int* __restrict__ ntype,
                          const float* __restrict__ emb) {
    int i = blockIdx.x * blockDim.x + threadIdx.x;
    if (i >= N_NODES * FEAT) return;
    int n = i / FEAT;
    int f = i - n * FEAT;
    float v = (f < IN_CH) ? x[(size_t)n * IN_CH + f]
                          : emb[ntype[n] * TYPE_EMB + (f - IN_CH)];
    g_A[(size_t)n * KTOT + f] = v;
}

// ---------------- tcgen05 bf16-split GEMM + bias + ReLU ----------------
#define SM_TILE0   8192
#define TILE_BYTES 16384
#define GEMM_SMEM  (SM_TILE0 + 8 * TILE_BYTES)   // 139264

__global__ __launch_bounds__(256, 1)
void k_gemm_mma(const float* __restrict__ bias, float* __restrict__ out) {
#if HAS_TCGEN05
    extern __shared__ char smem[];
    const uint32_t smem_base = smem_u32(smem);
    const int tid  = threadIdx.x;
    const int wid  = tid >> 5;
    const int lane = tid & 31;
    const int n0   = blockIdx.x * 128;

    if (tid == 0 && blockIdx.x == 0) g_mma_ok = 1;

    float* sBias  = reinterpret_cast<float*>(smem + 64);
    float* sScale = reinterpret_cast<float*>(smem + 576);

    if (wid == 0) {
        TCGEN05_ALLOC(smem_base + 0, 128);
        TCGEN05_RELINQ();
    }
    if (tid == 0) {
        MBARRIER_INIT(smem_base + 8, 1);
        MBARRIER_INIT(smem_base + 16, 1);
    }
    if (tid < 128) sBias[tid] = bias[tid];
    for (int i = tid; i < 128 * 9; i += 256) {
        int m = i / 9, s = i - m * 9;
        float sc = 1.0f;
        int node = n0 + m;
        if (s > 0 && node < N_NODES)
            sc = 1.0f / fmaxf(g_cnt[(size_t)node * N_REL + (s - 1)], 1.0f);
        sScale[i] = sc;
    }
    __syncthreads();

    uint32_t tmem;
    asm volatile("ld.shared.b32 %0, [%1];" : "=r"(tmem) : "r"(smem_base));

    int ph0 = 0, ph1 = 0;
    for (int i = 0; i < NCHUNK; ++i) {
        const int b = i & 1;
        if (i >= 2) {
            if (b == 0) { MBARRIER_WAIT_PARITY(smem_base + 8,  ph0); ph0 ^= 1; }
            else        { MBARRIER_WAIT_PARITY(smem_base + 16, ph1); ph1 ^= 1; }
        }
        char* tp = smem + SM_TILE0 + b * 4 * TILE_BYTES;
        const uint32_t tb = smem_base + SM_TILE0 + (uint32_t)b * 4 * TILE_BYTES;
        const int kbase = i * KCH;

        // ---- stage A (fp32 -> scaled bf16 hi/lo, SW128) ----
#pragma unroll
        for (int p = 0; p < 8; ++p) {
            int q   = p * 256 + tid;
            int row = q >> 4;
            int c4  = (q & 15) << 2;
            int k   = kbase + c4;
            float4 v = make_float4(0.f, 0.f, 0.f, 0.f);
            int node = n0 + row;
            if (node < N_NODES && k < KTOT)
                v = *reinterpret_cast<const float4*>(g_A + (size_t)node * KTOT + k);
            int slot = k / FEAT; if (slot > 8) slot = 8;
            float sc = sScale[row * 9 + slot];
            float f0 = v.x * sc, f1 = v.y * sc, f2 = v.z * sc, f3 = v.w * sc;
            __nv_bfloat162 h01 = __floats2bfloat162_rn(f0, f1);
            __nv_bfloat162 h23 = __floats2bfloat162_rn(f2, f3);
            float r0 = f0 - __bfloat162float(h01.x);
            float r1 = f1 - __bfloat162float(h01.y);
            float r2 = f2 - __bfloat162float(h23.x);
            float r3 = f3 - __bfloat162float(h23.y);
            __nv_bfloat162 l01 = __floats2bfloat162_rn(r0, r1);
            __nv_bfloat162 l23 = __floats2bfloat162_rn(r2, r3);
            uint32_t off = (uint32_t)(row * 128 + c4 * 2);
            uint32_t sw  = off ^ ((off >> 3) & 0x70);
            uint2 hi2 = make_uint2(*reinterpret_cast<uint32_t*>(&h01),
                                   *reinterpret_cast<uint32_t*>(&h23));
            uint2 lo2 = make_uint2(*reinterpret_cast<uint32_t*>(&l01),
                                   *reinterpret_cast<uint32_t*>(&l23));
            *reinterpret_cast<uint2*>(tp + sw)              = hi2;
            *reinterpret_cast<uint2*>(tp + TILE_BYTES + sw) = lo2;
        }
        // ---- stage B ----
#pragma unroll
        for (int p = 0; p < 4; ++p) {
            int q   = p * 256 + tid;
            int row = q >> 3;
            int w   = q & 7;
            const uint4* sh = reinterpret_cast<const uint4*>(g_Bh + (size_t)row * KPAD + kbase);
            const uint4* sl = reinterpret_cast<const uint4*>(g_Bl + (size_t)row * KPAD + kbase);
            uint32_t off = (uint32_t)(row * 128 + w * 16);
            uint32_t sw  = off ^ ((off >> 3) & 0x70);
            *reinterpret_cast<uint4*>(tp + 2 * TILE_BYTES + sw) = sh[w];
            *reinterpret_cast<uint4*>(tp + 3 * TILE_BYTES + sw) = sl[w];
        }
        __syncthreads();

        if (wid == 0) {
            asm volatile("fence.proxy.async.shared::cta;" ::: "memory");
            if (elect_one()) {
                uint64_t dAh = MAKE_SMEM_DESC(tb);
                uint64_t dAl = MAKE_SMEM_DESC(tb + TILE_BYTES);
                uint64_t dBh = MAKE_SMEM_DESC(tb + 2 * TILE_BYTES);
                uint64_t dBl = MAKE_SMEM_DESC(tb + 3 * TILE_BYTES);
#pragma unroll
                for (int s = 0; s < 4; ++s) {
                    mma_f16_ss(tmem, dAh + s * 2, dBh + s * 2, (i > 0) || (s > 0));
                    mma_f16_ss(tmem, dAh + s * 2, dBl + s * 2, true);
                    mma_f16_ss(tmem, dAl + s * 2, dBh + s * 2, true);
                }
                TCGEN05_COMMIT(smem_base + 8 + (uint32_t)b * 8);
            }
        }
    }

    MBARRIER_WAIT_PARITY(smem_base + 8,  ph0);
    MBARRIER_WAIT_PARITY(smem_base + 16, ph1);
    TCGEN05_FENCE_AFTER();

    // ---- epilogue ----
    {
        int rsub = wid & 3;
        int c0   = (wid >> 2) * 64;
        int node = n0 + rsub * 32 + lane;
#pragma unroll
        for (int g = 0; g < 2; ++g) {
            uint32_t regs[32];
            TCGEN05_LD_32X32B_X32(regs, tmem + (uint32_t)(c0 + g * 32));
            TCGEN05_WAIT_LD();
            if (node < N_NODES) {
                float* op = out + (size_t)node * OUT_CH + c0 + g * 32;
#pragma unroll
                for (int j4 = 0; j4 < 8; ++j4) {
                    float4 o;
                    o.x = fmaxf(__uint_as_float(regs[j4 * 4 + 0]) + sBias[c0 + g * 32 + j4 * 4 + 0], 0.f);
                    o.y = fmaxf(__uint_as_float(regs[j4 * 4 + 1]) + sBias[c0 + g * 32 + j4 * 4 + 1], 0.f);
                    o.z = fmaxf(__uint_as_float(regs[j4 * 4 + 2]) + sBias[c0 + g * 32 + j4 * 4 + 2], 0.f);
                    o.w = fmaxf(__uint_as_float(regs[j4 * 4 + 3]) + sBias[c0 + g * 32 + j4 * 4 + 3], 0.f);
                    *reinterpret_cast<float4*>(op + j4 * 4) = o;
                }
            }
        }
    }
    TCGEN05_FENCE_BEFORE();
    __syncthreads();
    if (tid == 0) {
        MBARRIER_INVAL(smem_base + 8);
        MBARRIER_INVAL(smem_base + 16);
    }
    __syncthreads();
    if (wid == 0) TCGEN05_DEALLOC(tmem, 128);
#else
    if (threadIdx.x == 0 && blockIdx.x == 0) g_mma_ok = 0;
#endif
}

// ---------------- fp32 fallback GEMM ----------------
#define BM 128
#define BK 32

__global__ __launch_bounds__(256, 2)
void k_gemm_fp32(const float* __restrict__ bias, float* __restrict__ out) {
    if (g_mma_ok) return;

    __shared__ float As[BK][BM + 4];
    __shared__ float Bs[BK][OUT_CH];
    __shared__ float sScale[BM][NSLOT + 1];

    const int tid = threadIdx.x;
    const int n0  = blockIdx.x * BM;
    const int ty  = tid >> 4;
    const int tx  = tid & 15;

    for (int i = tid; i < BM * NSLOT; i += 256) {
        int m = i / NSLOT, s = i - m * NSLOT;
        float sc = 1.0f;
        int node = n0 + m;
        if (s > 0 && node < N_NODES)
            sc = 1.0f / fmaxf(g_cnt[(size_t)node * N_REL + (s - 1)], 1.0f);
        sScale[m][s] = sc;
    }
    float bb[8];
#pragma unroll
    for (int j = 0; j < 8; ++j) bb[j] = bias[tx * 8 + j];
    float acc[8][8];
#pragma unroll
    for (int i = 0; i < 8; ++i)
#pragma unroll
        for (int j = 0; j < 8; ++j) acc[i][j] = 0.f;
    __syncthreads();

    for (int kt = 0; kt < KTOT / BK; ++kt) {
        const int k0   = kt * BK;
        const int slot = k0 / FEAT;
#pragma unroll
        for (int p = 0; p < 4; ++p) {
            int q = p * 256 + tid;
            int m = q >> 3;
            int kq = (q & 7) * 4;
            float4 v = make_float4(0.f, 0.f, 0.f, 0.f);
            int node = n0 + m;
            if (node < N_NODES)
                v = *reinterpret_cast<const float4*>(g_A + (size_t)node * KTOT + k0 + kq);
            float sc = sScale[m][slot];
            As[kq + 0][m] = v.x * sc; As[kq + 1][m] = v.y * sc;
            As[kq + 2][m] = v.z * sc; As[kq + 3][m] = v.w * sc;
        }
#pragma unroll
        for (int p = 0; p < 4; ++p) {
            int q = p * 256 + tid;
            int kI = q >> 5;
            int n4 = (q & 31) * 4;
            *reinterpret_cast<float4*>(&Bs[kI][n4]) =
                *reinterpret_cast<const float4*>(g_W + (size_t)(k0 + kI) * OUT_CH + n4);
        }
        __syncthreads();
#pragma unroll 8
        for (int kk = 0; kk < BK; ++kk) {
            float4 a0 = *reinterpret_cast<const float4*>(&As[kk][ty * 8]);
            float4 a1 = *reinterpret_cast<const float4*>(&As[kk][ty * 8 + 4]);
            float4 b0 = *reinterpret_cast<const float4*>(&Bs[kk][tx * 8]);
            float4 b1 = *reinterpret_cast<const float4*>(&Bs[kk][tx * 8 + 4]);
            float a[8] = {a0.x, a0.y, a0.z, a0.w, a1.x, a1.y, a1.z, a1.w};
            float b[8] = {b0.x, b0.y, b0.z, b0.w, b1.x, b1.y, b1.z, b1.w};
#pragma unroll
            for (int i = 0; i < 8; ++i)
#pragma unroll
                for (int j = 0; j < 8; ++j)
                    acc[i][j] = fmaf(a[i], b[j], acc[i][j]);
        }
        __syncthreads();
    }
#pragma unroll
    for (int i = 0; i < 8; ++i) {
        int node = n0 + ty * 8 + i;
        if (node >= N_NODES) continue;
        float* op = out + (size_t)node * OUT_CH + tx * 8;
#pragma unroll
        for (int j = 0; j < 8; ++j)
            op[j] = fmaxf(acc[i][j] + bb[j], 0.f);
    }
}

// ---------------- launch ----------------
extern "C" void kernel_launch(void* const* d_in, const int* in_sizes, int n_in,
                              void* d_out, int out_size) {
    const float* x      = (const float*)d_in[0];
    const int*   ntype  = (const int*)  d_in[1];
    const int*   eidx   = (const int*)  d_in[2];
    const int*   etype  = (const int*)  d_in[3];
    const float* emb    = (const float*)d_in[4];
    const float* bases  = (const float*)d_in[5];
    const float* comp   = (const float*)d_in[6];
    const float* root_w = (const float*)d_in[7];
    const float* bias   = (const float*)d_in[8];
    float*       out    = (float*)d_out;

    static bool attr_done = false;
    if (!attr_done) {
        cudaFuncSetAttribute(k_gemm_mma, cudaFuncAttributeMaxDynamicSharedMemorySize, GEMM_SMEM);
        attr_done = true;
    }

    // CSR build
    k_zero_meta<<<(NKEY + 255) / 256, 256>>>();
    k_hist<<<(N_EDGES + 255) / 256, 256>>>(eidx, etype);
    k_scan1<<<NSCANBLK, 1024>>>();
    k_scan2<<<1, 1024>>>();
    k_scan3<<<(NKEY + 255) / 256, 256>>>();
    // weights + h (independent of CSR)
    k_build_wt<<<(OUT_CH * KPAD + 255) / 256, 256>>>(bases, comp, root_w);
    k_build_h<<<(N_NODES * FEAT + 255) / 256, 256>>>(x, ntype, emb);
    // sort edges by (dst, rel)
    k_scatter_pos<<<(N_EDGES + 255) / 256, 256>>>(eidx, etype);
    // warp-per-(dst,rel) aggregation (writes all relation slots + counts)
    k_aggregate<<<(NKEY * 32 + 255) / 256, 256>>>();
    // GEMM + epilogue
    k_gemm_mma<<<(N_NODES + 127) / 128, 256, GEMM_SMEM>>>(bias, out);
    k_gemm_fp32<<<(N_NODES + BM - 1) / BM, 256>>>(bias, out);
}

// round 5
// speedup vs baseline: 2.5223x; 1.0995x over previous
#include <cuda_runtime.h>
#include <cuda_bf16.h>
#include <cstdint>

#define N_NODES 100000
#define N_EDGES 1600000
#define IN_CH   128
#define TYPE_EMB 32
#define FEAT    160
#define OUT_CH  128
#define N_REL   8
#define N_BASES 8
#define NSLOT   (N_REL + 1)
#define KTOT    (FEAT * NSLOT)   // 1440
#define KPAD    1472             // 23 * 64
#define KCH     64
#define NCHUNK  23
#define NKEY    (N_NODES * N_REL)        // 800000
#define NSCANBLK ((NKEY + 1023) / 1024)  // 782

// Arch-feature gate: tcgen05 only exists on the 'a' targets.
#if defined(__CUDA_ARCH_FEAT_SM103_ALL) || defined(__CUDA_ARCH_FEAT_SM100_ALL) || \
    defined(__CUDA_ARCH_FEAT_SM101_ALL) || \
    (defined(__CUDA_ARCH_SPECIFIC__) && (__CUDA_ARCH_SPECIFIC__ >= 1000))
#define HAS_TCGEN05 1
#else
#define HAS_TCGEN05 0
#endif

// ---------------- device scratch ----------------
__device__ float g_h[(size_t)N_NODES * FEAT];            // fp32 h (gather source)
__device__ __nv_bfloat16 g_Ah[(size_t)N_NODES * KPAD];   // scaled A hi (bf16)
__device__ __nv_bfloat16 g_Al[(size_t)N_NODES * KPAD];   // scaled A lo (bf16)
__device__ float g_W[KTOT * OUT_CH];                     // fp32 (fallback path)
__device__ __nv_bfloat16 g_Bh[OUT_CH * KPAD];            // W^T hi, [o][k]
__device__ __nv_bfloat16 g_Bl[OUT_CH * KPAD];            // W^T lo
__device__ int g_mma_ok;

// CSR scratch
__device__ int g_hist[NKEY];
__device__ int g_rowptr[NKEY + 1];
__device__ int g_cursor[NKEY];
__device__ int g_aux[NSCANBLK];
__device__ int g_auxs[NSCANBLK];
__device__ int g_esrc[N_EDGES];

// ================= PTX helpers =================
__device__ __forceinline__ uint32_t smem_u32(const void* p) {
    uint32_t a;
    asm("{ .reg .u64 t; cvta.to.shared.u64 t, %1; cvt.u32.u64 %0, t; }" : "=r"(a) : "l"(p));
    return a;
}
#define MBARRIER_INIT(addr, cnt) \
    asm volatile("mbarrier.init.shared.b64 [%0], %1;" :: "r"((uint32_t)(addr)), "r"((uint32_t)(cnt)) : "memory")
#define MBARRIER_INVAL(addr) \
    asm volatile("mbarrier.inval.shared.b64 [%0];" :: "r"((uint32_t)(addr)) : "memory")
#define MBARRIER_WAIT_PARITY(mbar_smem_addr, phase_parity) do { \
    uint32_t _mbar = (uint32_t)(mbar_smem_addr); \
    uint32_t _parity = (uint32_t)(phase_parity); \
    uint32_t _done; \
    asm volatile( \
        "{\n\t.reg .pred p;\n\t" \
        "mbarrier.try_wait.parity.acquire.cta.shared::cta.b64 p, [%1], %2;\n\t" \
        "selp.b32 %0, 1, 0, p;\n\t}" \
        : "=r"(_done) : "r"(_mbar), "r"(_parity) : "memory"); \
    if (!_done) { \
        asm volatile( \
            "{\n\t.reg .pred P1;\n\t" \
            "WAIT_LOOP_%=:\n\t" \
            "mbarrier.try_wait.parity.acquire.cta.shared::cta.b64 P1, [%0], %1, 0x989680;\n\t" \
            "@P1 bra.uni WAIT_DONE_%=;\n\t" \
            "bra.uni WAIT_LOOP_%=;\n\t" \
            "WAIT_DONE_%=:\n\t}" \
            :: "r"(_mbar), "r"(_parity) : "memory"); \
    } \
} while(0)

#if HAS_TCGEN05
__device__ __forceinline__ uint32_t elect_one() {
    uint32_t pred;
    asm volatile("{\n\t.reg .pred p;\n\telect.sync _|p, 0xFFFFFFFF;\n\tselp.b32 %0, 1, 0, p;\n\t}" : "=r"(pred));
    return pred;
}
#define TCGEN05_ALLOC(smem_addr, nCols) \
    asm volatile("tcgen05.alloc.cta_group::1.sync.aligned.shared::cta.b32 [%0], %1;" \
        :: "r"((uint32_t)(smem_addr)), "r"((uint32_t)(nCols)) : "memory")
#define TCGEN05_DEALLOC(tmem_addr, nCols) \
    asm volatile("tcgen05.dealloc.cta_group::1.sync.aligned.b32 %0, %1;" :: "r"(tmem_addr), "r"((uint32_t)(nCols)))
#define TCGEN05_RELINQ() \
    asm volatile("tcgen05.relinquish_alloc_permit.cta_group::1.sync.aligned;")
#define TCGEN05_COMMIT(mbar) \
    asm volatile("tcgen05.commit.cta_group::1.mbarrier::arrive::one.shared::cluster.b64 [%0];" \
        :: "r"((uint32_t)(mbar)) : "memory")
#define TCGEN05_FENCE_AFTER()  asm volatile("tcgen05.fence::after_thread_sync;" ::: "memory")
#define TCGEN05_FENCE_BEFORE() asm volatile("tcgen05.fence::before_thread_sync;" ::: "memory")
#define TCGEN05_WAIT_LD() asm volatile("tcgen05.wait::ld.sync.aligned;" ::: "memory")
#define TCGEN05_LD_32X32B_X32(r, tmem_addr) \
    asm volatile( \
        "tcgen05.ld.sync.aligned.32x32b.x32.b32 " \
        "{%0, %1, %2, %3, %4, %5, %6, %7, " \
        " %8, %9, %10, %11, %12, %13, %14, %15, " \
        " %16, %17, %18, %19, %20, %21, %22, %23, " \
        " %24, %25, %26, %27, %28, %29, %30, %31}, [%32];" \
        : "=r"((r)[0]),  "=r"((r)[1]),  "=r"((r)[2]),  "=r"((r)[3]), \
          "=r"((r)[4]),  "=r"((r)[5]),  "=r"((r)[6]),  "=r"((r)[7]), \
          "=r"((r)[8]),  "=r"((r)[9]),  "=r"((r)[10]), "=r"((r)[11]), \
          "=r"((r)[12]), "=r"((r)[13]), "=r"((r)[14]), "=r"((r)[15]), \
          "=r"((r)[16]), "=r"((r)[17]), "=r"((r)[18]), "=r"((r)[19]), \
          "=r"((r)[20]), "=r"((r)[21]), "=r"((r)[22]), "=r"((r)[23]), \
          "=r"((r)[24]), "=r"((r)[25]), "=r"((r)[26]), "=r"((r)[27]), \
          "=r"((r)[28]), "=r"((r)[29]), "=r"((r)[30]), "=r"((r)[31]) \
        : "r"(tmem_addr))

static constexpr uint64_t SMEM_DESC_BASE_SW128 =
    (uint64_t(2)  << 61) | (uint64_t(1) << 46) | (uint64_t(64) << 32) | (uint64_t(1) << 16);
#define MAKE_SMEM_DESC(base_addr) (SMEM_DESC_BASE_SW128 | ((uint64_t)((base_addr) >> 4) & 0x3FFF))

#define MMA_IDESC 0x8200490u

__device__ __forceinline__ void mma_f16_ss(uint32_t d, uint64_t a_desc, uint64_t b_desc, bool acc) {
    uint32_t en = acc ? 1u : 0u;
    asm volatile(
        "{\n\t.reg .pred p;\n\t"
        "setp.ne.u32 p, %5, 0;\n\t"
        "tcgen05.mma.cta_group::1.kind::f16 [%0], %1, %2, %3, {%4, %4, %4, %4}, p;\n\t"
        "}"
        :: "r"(d), "l"(a_desc), "l"(b_desc), "r"(MMA_IDESC), "r"(0u), "r"(en)
        : "memory");
}
#endif  // HAS_TCGEN05

// ---------------- CSR pipeline ----------------
__global__ void k_zero_meta() {
    int i = blockIdx.x * blockDim.x + threadIdx.x;
    if (i < NKEY) g_hist[i] = 0;
}

__global__ void k_hist(const int* __restrict__ edge_index,
                       const int* __restrict__ edge_type) {
    int e = blockIdx.x * blockDim.x + threadIdx.x;
    if (e >= N_EDGES) return;
    int dst = edge_index[N_EDGES + e];
    int r   = edge_type[e];
    atomicAdd(&g_hist[dst * N_REL + r], 1);
}

__global__ void k_scan1() {
    __shared__ int s[1024];
    int tid = threadIdx.x;
    int i = blockIdx.x * 1024 + tid;
    int v = (i < NKEY) ? g_hist[i] : 0;
    s[tid] = v;
    __syncthreads();
#pragma unroll
    for (int o = 1; o < 1024; o <<= 1) {
        int t = (tid >= o) ? s[tid - o] : 0;
        __syncthreads();
        s[tid] += t;
        __syncthreads();
    }
    if (i < NKEY) g_rowptr[i] = s[tid] - v;
    if (tid == 1023) g_aux[blockIdx.x] = s[1023];
}

__global__ void k_scan2() {
    __shared__ int s[1024];
    int tid = threadIdx.x;
    int v = (tid < NSCANBLK) ? g_aux[tid] : 0;
    s[tid] = v;
    __syncthreads();
#pragma unroll
    for (int o = 1; o < 1024; o <<= 1) {
        int t = (tid >= o) ? s[tid - o] : 0;
        __syncthreads();
        s[tid] += t;
        __syncthreads();
    }
    if (tid < NSCANBLK) g_auxs[tid] = s[tid] - v;
}

__global__ void k_scan3() {
    int i = blockIdx.x * blockDim.x + threadIdx.x;
    if (i < NKEY) {
        int v = g_rowptr[i] + g_auxs[i >> 10];
        g_rowptr[i] = v;
        g_cursor[i] = v;
    }
    if (i == 0) g_rowptr[NKEY] = N_EDGES;
}

__global__ void k_scatter_pos(const int* __restrict__ edge_index,
                              const int* __restrict__ edge_type) {
    int e = blockIdx.x * blockDim.x + threadIdx.x;
    if (e >= N_EDGES) return;
    int src = edge_index[e];
    int dst = edge_index[N_EDGES + e];
    int r   = edge_type[e];
    int pos = atomicAdd(&g_cursor[dst * N_REL + r], 1);
    g_esrc[pos] = src;
}

// ---------------- aggregation: warp per (dst,rel), fp32 accumulate, scaled bf16 hi/lo out ----------------
__global__ __launch_bounds__(256)
void k_aggregate() {
    int w    = (blockIdx.x * blockDim.x + threadIdx.x) >> 5;
    int lane = threadIdx.x & 31;
    if (w >= NKEY) return;
    int beg = g_rowptr[w];
    int end = g_rowptr[w + 1];
    float a0 = 0.f, a1 = 0.f, a2 = 0.f, a3 = 0.f, a4 = 0.f;
    for (int e = beg; e < end; ++e) {
        int src = g_esrc[e];
        const float* hp = g_h + (size_t)src * FEAT;
        a0 += hp[lane];
        a1 += hp[lane + 32];
        a2 += hp[lane + 64];
        a3 += hp[lane + 96];
        a4 += hp[lane + 128];
    }
    float sc = 1.0f / fmaxf((float)(end - beg), 1.0f);
    a0 *= sc; a1 *= sc; a2 *= sc; a3 *= sc; a4 *= sc;

    int dst = w >> 3;
    int r   = w & 7;
    size_t base = (size_t)dst * KPAD + FEAT + (size_t)r * FEAT;
    __nv_bfloat16* oh = g_Ah + base;
    __nv_bfloat16* ol = g_Al + base;
    __nv_bfloat16 h0 = __float2bfloat16(a0);
    __nv_bfloat16 h1 = __float2bfloat16(a1);
    __nv_bfloat16 h2 = __float2bfloat16(a2);
    __nv_bfloat16 h3 = __float2bfloat16(a3);
    __nv_bfloat16 h4 = __float2bfloat16(a4);
    oh[lane]       = h0;
    oh[lane + 32]  = h1;
    oh[lane + 64]  = h2;
    oh[lane + 96]  = h3;
    oh[lane + 128] = h4;
    ol[lane]       = __float2bfloat16(a0 - __bfloat162float(h0));
    ol[lane + 32]  = __float2bfloat16(a1 - __bfloat162float(h1));
    ol[lane + 64]  = __float2bfloat16(a2 - __bfloat162float(h2));
    ol[lane + 96]  = __float2bfloat16(a3 - __bfloat162float(h3));
    ol[lane + 128] = __float2bfloat16(a4 - __bfloat162float(h4));
}

// ---------------- weights (fp32 + bf16 hi/lo transposed) ----------------
__global__ void k_build_wt(const float* __restrict__ bases,
                           const float* __restrict__ comp,
                           const float* __restrict__ root_w) {
    int idx = blockIdx.x * blockDim.x + threadIdx.x;
    if (idx >= OUT_CH * KPAD) return;
    int o = idx / KPAD;
    int k = idx - o * KPAD;
    float v = 0.f;
    if (k < FEAT) {
        v = root_w[k * OUT_CH + o];
    } else if (k < KTOT) {
        int r = k / FEAT - 1;
        int f = k - (r + 1) * FEAT;
#pragma unroll
        for (int b = 0; b < N_BASES; ++b)
            v = fmaf(comp[r * N_BASES + b], bases[((size_t)b * FEAT + f) * OUT_CH + o], v);
    }
    __nv_bfloat16 hi = __float2bfloat16(v);
    g_Bh[idx] = hi;
    g_Bl[idx] = __float2bfloat16(v - __bfloat162float(hi));
    if (k < KTOT) g_W[k * OUT_CH + o] = v;
}

// ---------------- h build: fp32 g_h + slot0 hi/lo + zero pads ----------------
#define PADF 192   // FEAT + 32 pad columns handled per node
__global__ void k_build_h(const float* __restrict__ x,
                          const int* __restrict__ ntype,
                          const float* __restrict__ emb) {
    int i = blockIdx.x * blockDim.x + threadIdx.x;
    if (i >= N_NODES * PADF) return;
    int n = i / PADF;
    int f = i - n * PADF;
    if (f < FEAT) {
        float v = (f < IN_CH) ? x[(size_t)n * IN_CH + f]
                              : emb[ntype[n] * TYPE_EMB + (f - IN_CH)];
        g_h[(size_t)n * FEAT + f] = v;
        __nv_bfloat16 hi = __float2bfloat16(v);
        g_Ah[(size_t)n * KPAD + f] = hi;
        g_Al[(size_t)n * KPAD + f] = __float2bfloat16(v - __bfloat162float(hi));
    } else {
        // pad columns 1440..1471
        size_t k = (size_t)n * KPAD + (KTOT + (f - FEAT));
        g_Ah[k] = __float2bfloat16(0.f);
        g_Al[k] = __float2bfloat16(0.f);
    }
}

// ---------------- tcgen05 bf16-split GEMM + bias + ReLU ----------------
#define SM_TILE0   8192
#define TILE_BYTES 16384
#define GEMM_SMEM  (SM_TILE0 + 8 * TILE_BYTES)   // 139264

__global__ __launch_bounds__(256, 1)
void k_gemm_mma(const float* __restrict__ bias, float* __restrict__ out) {
#if HAS_TCGEN05
    extern __shared__ char smem[];
    const uint32_t smem_base = smem_u32(smem);
    const int tid  = threadIdx.x;
    const int wid  = tid >> 5;
    const int lane = tid & 31;
    const int n0   = blockIdx.x * 128;

    if (tid == 0 && blockIdx.x == 0) g_mma_ok = 1;

    float* sBias = reinterpret_cast<float*>(smem + 64);

    if (wid == 0) {
        TCGEN05_ALLOC(smem_base + 0, 128);
        TCGEN05_RELINQ();
    }
    if (tid == 0) {
        MBARRIER_INIT(smem_base + 8, 1);
        MBARRIER_INIT(smem_base + 16, 1);
    }
    if (tid < 128) sBias[tid] = bias[tid];
    __syncthreads();

    uint32_t tmem;
    asm volatile("ld.shared.b32 %0, [%1];" : "=r"(tmem) : "r"(smem_base));

    const bool full = (n0 + 128 <= N_NODES);
    int ph0 = 0, ph1 = 0;
    for (int i = 0; i < NCHUNK; ++i) {
        const int b = i & 1;
        if (i >= 2) {
            if (b == 0) { MBARRIER_WAIT_PARITY(smem_base + 8,  ph0); ph0 ^= 1; }
            else        { MBARRIER_WAIT_PARITY(smem_base + 16, ph1); ph1 ^= 1; }
        }
        char* tp = smem + SM_TILE0 + b * 4 * TILE_BYTES;
        const uint32_t tb = smem_base + SM_TILE0 + (uint32_t)b * 4 * TILE_BYTES;
        const int kbase = i * KCH;

        // ---- stage A: pure swizzled copy of bf16 hi/lo tiles (128 rows x 128B) ----
#pragma unroll
        for (int p = 0; p < 4; ++p) {
            int q   = p * 256 + tid;       // 0..1023
            int row = q >> 3;              // 0..127
            int w16 = (q & 7) * 16;        // byte seg 0..112
            uint32_t off = (uint32_t)(row * 128 + w16);
            uint32_t sw  = off ^ ((off >> 3) & 0x70);
            uint4 vh = make_uint4(0, 0, 0, 0), vl = make_uint4(0, 0, 0, 0);
            if (full || (n0 + row) < N_NODES) {
                const char* ph = (const char*)(g_Ah + (size_t)(n0 + row) * KPAD + kbase) + w16;
                const char* pl = (const char*)(g_Al + (size_t)(n0 + row) * KPAD + kbase) + w16;
                vh = *reinterpret_cast<const uint4*>(ph);
                vl = *reinterpret_cast<const uint4*>(pl);
            }
            *reinterpret_cast<uint4*>(tp + sw)              = vh;  // Ah
            *reinterpret_cast<uint4*>(tp + TILE_BYTES + sw) = vl;  // Al
        }
        // ---- stage B: swizzled copy of bf16 hi/lo weight tiles ----
#pragma unroll
        for (int p = 0; p < 4; ++p) {
            int q   = p * 256 + tid;
            int row = q >> 3;
            int w   = q & 7;
            const uint4* sh = reinterpret_cast<const uint4*>(g_Bh + (size_t)row * KPAD + kbase);
            const uint4* sl = reinterpret_cast<const uint4*>(g_Bl + (size_t)row * KPAD + kbase);
            uint32_t off = (uint32_t)(row * 128 + w * 16);
            uint32_t sw  = off ^ ((off >> 3) & 0x70);
            *reinterpret_cast<uint4*>(tp + 2 * TILE_BYTES + sw) = sh[w];
            *reinterpret_cast<uint4*>(tp + 3 * TILE_BYTES + sw) = sl[w];
        }
        __syncthreads();

        if (wid == 0) {
            asm volatile("fence.proxy.async.shared::cta;" ::: "memory");
            if (elect_one()) {
                uint64_t dAh = MAKE_SMEM_DESC(tb);
                uint64_t dAl = MAKE_SMEM_DESC(tb + TILE_BYTES);
                uint64_t dBh = MAKE_SMEM_DESC(tb + 2 * TILE_BYTES);
                uint64_t dBl = MAKE_SMEM_DESC(tb + 3 * TILE_BYTES);
#pragma unroll
                for (int s = 0; s < 4; ++s) {
                    mma_f16_ss(tmem, dAh + s * 2, dBh + s * 2, (i > 0) || (s > 0));
                    mma_f16_ss(tmem, dAh + s * 2, dBl + s * 2, true);
                    mma_f16_ss(tmem, dAl + s * 2, dBh + s * 2, true);
                }
                TCGEN05_COMMIT(smem_base + 8 + (uint32_t)b * 8);
            }
        }
    }

    MBARRIER_WAIT_PARITY(smem_base + 8,  ph0);
    MBARRIER_WAIT_PARITY(smem_base + 16, ph1);
    TCGEN05_FENCE_AFTER();

    // ---- epilogue ----
    {
        int rsub = wid & 3;
        int c0   = (wid >> 2) * 64;
        int node = n0 + rsub * 32 + lane;
#pragma unroll
        for (int g = 0; g < 2; ++g) {
            uint32_t regs[32];
            TCGEN05_LD_32X32B_X32(regs, tmem + (uint32_t)(c0 + g * 32));
            TCGEN05_WAIT_LD();
            if (node < N_NODES) {
                float* op = out + (size_t)node * OUT_CH + c0 + g * 32;
#pragma unroll
                for (int j4 = 0; j4 < 8; ++j4) {
                    float4 o;
                    o.x = fmaxf(__uint_as_float(regs[j4 * 4 + 0]) + sBias[c0 + g * 32 + j4 * 4 + 0], 0.f);
                    o.y = fmaxf(__uint_as_float(regs[j4 * 4 + 1]) + sBias[c0 + g * 32 + j4 * 4 + 1], 0.f);
                    o.z = fmaxf(__uint_as_float(regs[j4 * 4 + 2]) + sBias[c0 + g * 32 + j4 * 4 + 2], 0.f);
                    o.w = fmaxf(__uint_as_float(regs[j4 * 4 + 3]) + sBias[c0 + g * 32 + j4 * 4 + 3], 0.f);
                    *reinterpret_cast<float4*>(op + j4 * 4) = o;
                }
            }
        }
    }
    TCGEN05_FENCE_BEFORE();
    __syncthreads();
    if (tid == 0) {
        MBARRIER_INVAL(smem_base + 8);
        MBARRIER_INVAL(smem_base + 16);
    }
    __syncthreads();
    if (wid == 0) TCGEN05_DEALLOC(tmem, 128);
#else
    if (threadIdx.x == 0 && blockIdx.x == 0) g_mma_ok = 0;
#endif
}

// ---------------- fp32 fallback GEMM (A reconstructed = hi + lo, scale pre-applied) ----------------
#define BM 128
#define BK 32

__global__ __launch_bounds__(256, 2)
void k_gemm_fp32(const float* __restrict__ bias, float* __restrict__ out) {
    if (g_mma_ok) return;

    __shared__ float As[BK][BM + 4];
    __shared__ float Bs[BK][OUT_CH];

    const int tid = threadIdx.x;
    const int n0  = blockIdx.x * BM;
    const int ty  = tid >> 4;
    const int tx  = tid & 15;

    float bb[8];
#pragma unroll
    for (int j = 0; j < 8; ++j) bb[j] = bias[tx * 8 + j];
    float acc[8][8];
#pragma unroll
    for (int i = 0; i < 8; ++i)
#pragma unroll
        for (int j = 0; j < 8; ++j) acc[i][j] = 0.f;

    for (int kt = 0; kt < KTOT / BK; ++kt) {
        const int k0 = kt * BK;
#pragma unroll
        for (int p = 0; p < 4; ++p) {
            int q = p * 256 + tid;
            int m = q >> 3;
            int kq = (q & 7) * 4;
            float4 v = make_float4(0.f, 0.f, 0.f, 0.f);
            int node = n0 + m;
            if (node < N_NODES) {
                size_t base = (size_t)node * KPAD + k0 + kq;
#pragma unroll
                for (int z = 0; z < 4; ++z)
                    (&v.x)[z] = __bfloat162float(g_Ah[base + z]) + __bfloat162float(g_Al[base + z]);
            }
            As[kq + 0][m] = v.x; As[kq + 1][m] = v.y;
            As[kq + 2][m] = v.z; As[kq + 3][m] = v.w;
        }
#pragma unroll
        for (int p = 0; p < 4; ++p) {
            int q = p * 256 + tid;
            int kI = q >> 5;
            int n4 = (q & 31) * 4;
            *reinterpret_cast<float4*>(&Bs[kI][n4]) =
                *reinterpret_cast<const float4*>(g_W + (size_t)(k0 + kI) * OUT_CH + n4);
        }
        __syncthreads();
#pragma unroll 8
        for (int kk = 0; kk < BK; ++kk) {
            float4 a0 = *reinterpret_cast<const float4*>(&As[kk][ty * 8]);
            float4 a1 = *reinterpret_cast<const float4*>(&As[kk][ty * 8 + 4]);
            float4 b0 = *reinterpret_cast<const float4*>(&Bs[kk][tx * 8]);
            float4 b1 = *reinterpret_cast<const float4*>(&Bs[kk][tx * 8 + 4]);
            float a[8] = {a0.x, a0.y, a0.z, a0.w, a1.x, a1.y, a1.z, a1.w};
            float b[8] = {b0.x, b0.y, b0.z, b0.w, b1.x, b1.y, b1.z, b1.w};
#pragma unroll
            for (int i = 0; i < 8; ++i)
#pragma unroll
                for (int j = 0; j < 8; ++j)
                    acc[i][j] = fmaf(a[i], b[j], acc[i][j]);
        }
        __syncthreads();
    }
#pragma unroll
    for (int i = 0; i < 8; ++i) {
        int node = n0 + ty * 8 + i;
        if (node >= N_NODES) continue;
        float* op = out + (size_t)node * OUT_CH + tx * 8;
#pragma unroll
        for (int j = 0; j < 8; ++j)
            op[j] = fmaxf(acc[i][j] + bb[j], 0.f);
    }
}

// ---------------- launch ----------------
extern "C" void kernel_launch(void* const* d_in, const int* in_sizes, int n_in,
                              void* d_out, int out_size) {
    const float* x      = (const float*)d_in[0];
    const int*   ntype  = (const int*)  d_in[1];
    const int*   eidx   = (const int*)  d_in[2];
    const int*   etype  = (const int*)  d_in[3];
    const float* emb    = (const float*)d_in[4];
    const float* bases  = (const float*)d_in[5];
    const float* comp   = (const float*)d_in[6];
    const float* root_w = (const float*)d_in[7];
    const float* bias   = (const float*)d_in[8];
    float*       out    = (float*)d_out;

    static bool attr_done = false;
    if (!attr_done) {
        cudaFuncSetAttribute(k_gemm_mma, cudaFuncAttributeMaxDynamicSharedMemorySize, GEMM_SMEM);
        attr_done = true;
    }

    // CSR build
    k_zero_meta<<<(NKEY + 255) / 256, 256>>>();
    k_hist<<<(N_EDGES + 255) / 256, 256>>>(eidx, etype);
    k_scan1<<<NSCANBLK, 1024>>>();
    k_scan2<<<1, 1024>>>();
    k_scan3<<<(NKEY + 255) / 256, 256>>>();
    // weights + h (independent of CSR)
    k_build_wt<<<(OUT_CH * KPAD + 255) / 256, 256>>>(bases, comp, root_w);
    k_build_h<<<(N_NODES * PADF + 255) / 256, 256>>>(x, ntype, emb);
    // sort edges by (dst, rel)
    k_scatter_pos<<<(N_EDGES + 255) / 256, 256>>>(eidx, etype);
    // warp-per-(dst,rel) aggregation -> scaled bf16 hi/lo slots
    k_aggregate<<<(NKEY * 32 + 255) / 256, 256>>>();
    // GEMM + epilogue
    k_gemm_mma<<<(N_NODES + 127) / 128, 256, GEMM_SMEM>>>(bias, out);
    k_gemm_fp32<<<(N_NODES + BM - 1) / BM, 256>>>(bias, out);
}